// round 14
// baseline (speedup 1.0000x reference)
#include <cuda_runtime.h>

typedef unsigned long long u64;

#define NITER 31
#define BLOCK 256

__device__ double   g_sum   = 0.0;
__device__ unsigned g_count = 0;

__device__ __forceinline__ u64 pk2(float a, float b) {
    u64 r; asm("mov.b64 %0, {%1, %2};" : "=l"(r) : "f"(a), "f"(b)); return r;
}
__device__ __forceinline__ void up2(u64 v, float &a, float &b) {
    asm("mov.b64 {%0, %1}, %2;" : "=f"(a), "=f"(b) : "l"(v));
}
__device__ __forceinline__ u64 ffma2(u64 a, u64 b, u64 c) {
    u64 d; asm("fma.rn.f32x2 %0, %1, %2, %3;" : "=l"(d) : "l"(a), "l"(b), "l"(c)); return d;
}
__device__ __forceinline__ u64 fmul2(u64 a, u64 b) {
    u64 d; asm("mul.rn.f32x2 %0, %1, %2;" : "=l"(d) : "l"(a), "l"(b)); return d;
}
__device__ __forceinline__ u64 fsub2(u64 a, u64 b) {
    u64 d; asm("sub.rn.f32x2 %0, %1, %2;" : "=l"(d) : "l"(a), "l"(b)); return d;
}
__device__ __forceinline__ u64 fadd2(u64 a, u64 b) {
    u64 d; asm("add.rn.f32x2 %0, %1, %2;" : "=l"(d) : "l"(a), "l"(b)); return d;
}
__device__ __forceinline__ float frcp_(float x) {
    float r; asm("rcp.approx.f32 %0, %1;" : "=f"(r) : "f"(x)); return r;
}
// sc halves = 2^(127 - exp(q_half)) — pure u64 integer arithmetic, exact.
__device__ __forceinline__ u64 exp_scale(u64 q) {
    return 0x7F0000007F000000ULL - (q & 0x7F8000007F800000ULL);
}
// Force positive-normal q's exponent to 127 per half (== fmul2(q, exp_scale(q))).
__device__ __forceinline__ u64 set_exp1(u64 q) {
    return (q & 0x807FFFFF807FFFFFULL) | 0x3F8000003F800000ULL;
}
#define NEGMASK2 0x8000000080000000ULL

// Scalar setup for the tail path (with degenerate guard).
struct RayQ { float E, s, i4; };
__device__ __forceinline__ RayQ setup_ray(
    float px, float py, float pz, float wx, float wy, float wz,
    float r00, float r10, float r20, float tx, float ty, float tz,
    float c, float mc, float twoc)
{
    float qx = px - tx, qy = py - ty, qz = pz - tz;
    float plx  = qx*r00 + qy*r10 + qz*r20;
    float vlx  = wx*r00 + wy*r10 + wz*r20;
    float ndot = fmaf(-qx, wx, fmaf(-qy, wy, -qz*wz));
    float nn2  = fmaf(-qx, qx, fmaf(-qy, qy, -qz*qz));
    float A  = fmaf(vlx*vlx, c, mc);
    float B  = fmaf(twoc, fmaf(plx, vlx, ndot), vlx);
    float C  = fmaf(c, fmaf(plx, plx, nn2), plx);
    if (A == 0.0f) { A = 1.0f; B = 1.0f; C = 0.0f; }
    RayQ o;
    float D = fmaf(A * C, -4.0f, B * B);
    o.E  = D + 1.0f;
    o.s  = B;
    o.i4 = frcp_(4.0f * A);
    return o;
}

// Packed (2-ray) setup: produces E, s0(=B), i4 pairs from packed components.
__device__ __forceinline__ void setup_pair(
    u64 PX, u64 PY, u64 PZ, u64 WX, u64 WY, u64 WZ,
    u64 R00, u64 R10, u64 R20, u64 TX, u64 TY, u64 TZ,
    u64 CC, u64 MC, u64 TWOC, u64 M42, u64 FOUR2, u64 ONE2x,
    u64 &E, u64 &S, u64 &I4)
{
    u64 qx = fsub2(PX, TX), qy = fsub2(PY, TY), qz = fsub2(PZ, TZ);
    u64 plx = ffma2(qz, R20, ffma2(qy, R10, fmul2(qx, R00)));
    u64 vlx = ffma2(WZ, R20, ffma2(WY, R10, fmul2(WX, R00)));
    u64 dot = ffma2(qz, WZ, ffma2(qy, WY, fmul2(qx, WX)));   // (P-T).V
    u64 nn2 = ffma2(qz, qz, ffma2(qy, qy, fmul2(qx, qx)));   // |P-T|^2
    u64 ndot = dot ^ NEGMASK2;                                // exact negate
    u64 nn2n = nn2 ^ NEGMASK2;
    u64 A  = ffma2(fmul2(vlx, vlx), CC, MC);                  // c vlx^2 - c
    u64 B  = ffma2(TWOC, ffma2(plx, vlx, ndot), vlx);
    u64 C  = ffma2(CC, ffma2(plx, plx, nn2n), plx);
    u64 D  = ffma2(fmul2(A, C), M42, fmul2(B, B));            // B^2 - 4AC
    E = fadd2(D, ONE2x);
    S = B;
    u64 A4 = fmul2(A, FOUR2);
    float f0, f1; up2(A4, f0, f1);
    float i0 = (f0 == 0.0f) ? 0.0f : frcp_(f0);   // degenerate -> F = 0
    float i1 = (f1 == 0.0f) ? 0.0f : frcp_(f1);
    I4 = pk2(i0, i1);
}

__global__ void __launch_bounds__(BLOCK)
lm_kernel(const float* __restrict__ P, const float* __restrict__ V,
          const float* __restrict__ R, const float* __restrict__ T,
          const float* __restrict__ Cs, const float* __restrict__ loss_in,
          float* __restrict__ out, int n, double invN)
{
    const int g = blockIdx.x * BLOCK + threadIdx.x;   // 8 rays / thread
    const int base = g * 8;

    float ssum = 0.0f;

    if (base < n) {
        const float r00 = __ldg(R + 0), r10 = __ldg(R + 3), r20 = __ldg(R + 6);
        const float tx = __ldg(T + 0), ty = __ldg(T + 1), tz = __ldg(T + 2);
        const float c    = __ldg(Cs);
        const float mc   = -c;
        const float twoc = 2.0f * c;

        const u64 TWO2  = 0x4000000040000000ULL;  // (2, 2)
        const u64 ONE2  = 0x3F8000003F800000ULL;  // (1, 1)
        const u64 FOUR2 = 0x4080000040800000ULL;  // (4, 4)
        const u64 M42   = 0xC0800000C0800000ULL;  // (-4, -4)

        u64 E[4], p[4], q[4], I4[4];

        if (base + 8 <= n) {
            const u64 R00 = pk2(r00, r00), R10 = pk2(r10, r10), R20 = pk2(r20, r20);
            const u64 TX = pk2(tx, tx), TY = pk2(ty, ty), TZ = pk2(tz, tz);
            const u64 CC = pk2(c, c), MC = pk2(mc, mc), TWOC = pk2(twoc, twoc);

            const float4* P4 = (const float4*)P;
            const float4* V4 = (const float4*)V;
            #pragma unroll
            for (int h = 0; h < 2; ++h) {     // two 4-ray halves
                float4 a0 = P4[6*g + 3*h + 0], a1 = P4[6*g + 3*h + 1], a2 = P4[6*g + 3*h + 2];
                float4 b0 = V4[6*g + 3*h + 0], b1 = V4[6*g + 3*h + 1], b2 = V4[6*g + 3*h + 2];
                // pair A: rays (0,1) of this half
                setup_pair(pk2(a0.x, a0.w), pk2(a0.y, a1.x), pk2(a0.z, a1.y),
                           pk2(b0.x, b0.w), pk2(b0.y, b1.x), pk2(b0.z, b1.y),
                           R00, R10, R20, TX, TY, TZ, CC, MC, TWOC, M42, FOUR2, ONE2,
                           E[2*h], p[2*h], I4[2*h]);
                // pair B: rays (2,3) of this half
                setup_pair(pk2(a1.z, a2.y), pk2(a1.w, a2.z), pk2(a2.x, a2.w),
                           pk2(b1.z, b2.y), pk2(b1.w, b2.z), pk2(b2.x, b2.w),
                           R00, R10, R20, TX, TY, TZ, CC, MC, TWOC, M42, FOUR2, ONE2,
                           E[2*h+1], p[2*h+1], I4[2*h+1]);
            }
        } else {
            RayQ rq[8];
            #pragma unroll
            for (int k = 0; k < 8; ++k) {
                int i = base + k;
                if (i < n) {
                    rq[k] = setup_ray(P[3*i],P[3*i+1],P[3*i+2],
                                      V[3*i],V[3*i+1],V[3*i+2],
                                      r00,r10,r20, tx,ty,tz, c,mc,twoc);
                } else {
                    rq[k].E = 2.0f; rq[k].s = 1.0f; rq[k].i4 = 0.25f; // F ends 0
                }
            }
            #pragma unroll
            for (int k = 0; k < 4; ++k) {
                E[k]  = pk2(rq[2*k].E,  rq[2*k+1].E);
                p[k]  = pk2(rq[2*k].s,  rq[2*k+1].s);
                I4[k] = pk2(rq[2*k].i4, rq[2*k+1].i4);
            }
        }
        #pragma unroll
        for (int k = 0; k < 4; ++k) q[k] = ONE2;

        // Projective LM (R13-validated): s' = s(s^2+E)/(2s^2+1)
        //   p' = p (p^2 + E q^2),  q' = q (2 p^2 + q^2)
        // Exact common power-of-two renorm every 2nd iteration.
        #pragma unroll
        for (int it = 0; it < NITER; ++it) {
            #pragma unroll
            for (int k = 0; k < 4; ++k) {
                u64 pp = fmul2(p[k], p[k]);
                u64 qq = fmul2(q[k], q[k]);
                u64 u  = ffma2(E[k], qq, pp);    // p^2 + E q^2
                u64 v  = ffma2(pp, TWO2, qq);    // 2 p^2 + q^2
                p[k] = fmul2(p[k], u);
                q[k] = fmul2(q[k], v);
            }
            if (it & 1) {
                #pragma unroll
                for (int k = 0; k < 4; ++k) {
                    u64 sc = exp_scale(q[k]);    // 2^-k per half (int ops)
                    p[k] = fmul2(p[k], sc);      // exact
                    q[k] = set_exp1(q[k]);       // exact, alu pipe only
                }
            }
        }

        // Epilogue: s = p/q, F = (s^2 - D) i4 = (s^2 - E + 1) i4
        u64 ss = 0ULL;
        #pragma unroll
        for (int k = 0; k < 4; ++k) {
            float qa, qb; up2(q[k], qa, qb);
            u64 rq2 = pk2(frcp_(qa), frcp_(qb));
            u64 s  = fmul2(p[k], rq2);
            u64 qs = fmul2(s, s);
            u64 t  = fsub2(qs, E[k]);            // s^2 - D - 1
            u64 w  = fadd2(t, ONE2);             // s^2 - D
            u64 F  = fmul2(w, I4[k]);
            ss = ffma2(F, F, ss);
        }
        float sa, sb; up2(ss, sa, sb);
        ssum = sa + sb;
    }

    // Block tree reduction (float)
    #pragma unroll
    for (int o = 16; o > 0; o >>= 1)
        ssum += __shfl_xor_sync(0xffffffffu, ssum, o);
    __shared__ float wsum[BLOCK / 32];
    if ((threadIdx.x & 31) == 0) wsum[threadIdx.x >> 5] = ssum;
    __syncthreads();

    // Global double accumulation + last-block finalize (self-resetting for
    // identical behavior on every graph replay).
    if (threadIdx.x == 0) {
        float bsum = 0.0f;
        #pragma unroll
        for (int w = 0; w < BLOCK / 32; ++w) bsum += wsum[w];
        atomicAdd(&g_sum, (double)bsum);
        __threadfence();
        unsigned old = atomicAdd(&g_count, 1u);
        if (old == gridDim.x - 1) {
            __threadfence();
            double tot = g_sum;
            out[0] = (float)((double)loss_in[0] + tot * invN);
            g_sum = 0.0;
            __threadfence();
            g_count = 0;
        }
    }
}

extern "C" void kernel_launch(void* const* d_in, const int* in_sizes, int n_in,
                              void* d_out, int out_size)
{
    const float* P       = (const float*)d_in[0];
    const float* V       = (const float*)d_in[1];
    const float* R       = (const float*)d_in[2];
    const float* T       = (const float*)d_in[3];
    const float* c       = (const float*)d_in[4];
    const float* loss_in = (const float*)d_in[5];

    const int n = in_sizes[0] / 3;                 // number of rays
    int nthreads = (n + 7) / 8;                    // 8 rays per thread
    int nblocks  = (nthreads + BLOCK - 1) / BLOCK; // 2048 for N=4.19M

    lm_kernel<<<nblocks, BLOCK>>>(P, V, R, T, c, loss_in,
                                  (float*)d_out, n, 1.0 / (double)n);
}

// round 15
// speedup vs baseline: 1.0059x; 1.0059x over previous
#include <cuda_runtime.h>

typedef unsigned long long u64;

#define NITER 31
#define BLOCK 256

__device__ double   g_sum   = 0.0;
__device__ unsigned g_count = 0;

__device__ __forceinline__ u64 pk2(float a, float b) {
    u64 r; asm("mov.b64 %0, {%1, %2};" : "=l"(r) : "f"(a), "f"(b)); return r;
}
__device__ __forceinline__ void up2(u64 v, float &a, float &b) {
    asm("mov.b64 {%0, %1}, %2;" : "=f"(a), "=f"(b) : "l"(v));
}
__device__ __forceinline__ u64 ffma2(u64 a, u64 b, u64 c) {
    u64 d; asm("fma.rn.f32x2 %0, %1, %2, %3;" : "=l"(d) : "l"(a), "l"(b), "l"(c)); return d;
}
__device__ __forceinline__ u64 fmul2(u64 a, u64 b) {
    u64 d; asm("mul.rn.f32x2 %0, %1, %2;" : "=l"(d) : "l"(a), "l"(b)); return d;
}
__device__ __forceinline__ u64 fsub2(u64 a, u64 b) {
    u64 d; asm("sub.rn.f32x2 %0, %1, %2;" : "=l"(d) : "l"(a), "l"(b)); return d;
}
__device__ __forceinline__ u64 fadd2(u64 a, u64 b) {
    u64 d; asm("add.rn.f32x2 %0, %1, %2;" : "=l"(d) : "l"(a), "l"(b)); return d;
}
__device__ __forceinline__ float frcp_(float x) {
    float r; asm("rcp.approx.f32 %0, %1;" : "=f"(r) : "f"(x)); return r;
}
// sc halves = 2^(127 - exp(q_half)) — pure u64 integer arithmetic, exact.
__device__ __forceinline__ u64 exp_scale(u64 q) {
    return 0x7F0000007F000000ULL - (q & 0x7F8000007F800000ULL);
}
// Force positive-normal q's exponent to 127 per half (== fmul2(q, exp_scale(q))).
__device__ __forceinline__ u64 set_exp1(u64 q) {
    return (q & 0x807FFFFF807FFFFFULL) | 0x3F8000003F800000ULL;
}

// Per-ray quadratic setup (|V_local| = 1, rotation invariance; only col 0 of R):
//   A = -c(1 - vlx^2),  B = vlx + 2c(plx*vlx - (P-T).V),
//   C = plx + c(plx^2 - |P-T|^2),  D = B^2 - 4AC.
struct RayQ { float E, s, i4; };   // E = D+1, s0 = B, i4 = 1/(4A)

__device__ __forceinline__ RayQ setup_ray(
    float px, float py, float pz, float wx, float wy, float wz,
    float r00, float r10, float r20, float tx, float ty, float tz,
    float c, float mc, float twoc)
{
    float qx = px - tx, qy = py - ty, qz = pz - tz;
    float plx  = qx*r00 + qy*r10 + qz*r20;
    float vlx  = wx*r00 + wy*r10 + wz*r20;
    float ndot = fmaf(-qx, wx, fmaf(-qy, wy, -qz*wz));   // -(P-T).V
    float nn2  = fmaf(-qx, qx, fmaf(-qy, qy, -qz*qz));   // -|P-T|^2
    float A  = fmaf(vlx*vlx, c, mc);            // -c(1-vlx^2)
    float B  = fmaf(twoc, fmaf(plx, vlx, ndot), vlx);
    float C  = fmaf(c, fmaf(plx, plx, nn2), plx);
    if (A == 0.0f) { A = 1.0f; B = 1.0f; C = 0.0f; }     // degenerate guard
    RayQ o;
    float D = fmaf(A * C, -4.0f, B * B);        // D = B^2 - 4AC
    o.E  = D + 1.0f;
    o.s  = B;
    o.i4 = frcp_(4.0f * A);
    return o;
}

__global__ void __launch_bounds__(BLOCK)
lm_kernel(const float* __restrict__ P, const float* __restrict__ V,
          const float* __restrict__ R, const float* __restrict__ T,
          const float* __restrict__ Cs, const float* __restrict__ loss_in,
          float* __restrict__ out, int n, double invN)
{
    const int g = blockIdx.x * BLOCK + threadIdx.x;   // 8 rays / thread
    const int base = g * 8;

    float ssum = 0.0f;

    if (base < n) {
        const float r00 = __ldg(R + 0), r10 = __ldg(R + 3), r20 = __ldg(R + 6);
        const float tx = __ldg(T + 0), ty = __ldg(T + 1), tz = __ldg(T + 2);
        const float c    = __ldg(Cs);
        const float mc   = -c;
        const float twoc = 2.0f * c;

        RayQ rq[8];
        if (base + 8 <= n) {
            const float4* P4 = (const float4*)P;
            const float4* V4 = (const float4*)V;
            {
                float4 a0 = P4[6*g + 0], a1 = P4[6*g + 1], a2 = P4[6*g + 2];
                float4 b0 = V4[6*g + 0], b1 = V4[6*g + 1], b2 = V4[6*g + 2];
                rq[0] = setup_ray(a0.x,a0.y,a0.z, b0.x,b0.y,b0.z, r00,r10,r20, tx,ty,tz, c,mc,twoc);
                rq[1] = setup_ray(a0.w,a1.x,a1.y, b0.w,b1.x,b1.y, r00,r10,r20, tx,ty,tz, c,mc,twoc);
                rq[2] = setup_ray(a1.z,a1.w,a2.x, b1.z,b1.w,b2.x, r00,r10,r20, tx,ty,tz, c,mc,twoc);
                rq[3] = setup_ray(a2.y,a2.z,a2.w, b2.y,b2.z,b2.w, r00,r10,r20, tx,ty,tz, c,mc,twoc);
            }
            {
                float4 a0 = P4[6*g + 3], a1 = P4[6*g + 4], a2 = P4[6*g + 5];
                float4 b0 = V4[6*g + 3], b1 = V4[6*g + 4], b2 = V4[6*g + 5];
                rq[4] = setup_ray(a0.x,a0.y,a0.z, b0.x,b0.y,b0.z, r00,r10,r20, tx,ty,tz, c,mc,twoc);
                rq[5] = setup_ray(a0.w,a1.x,a1.y, b0.w,b1.x,b1.y, r00,r10,r20, tx,ty,tz, c,mc,twoc);
                rq[6] = setup_ray(a1.z,a1.w,a2.x, b1.z,b1.w,b2.x, r00,r10,r20, tx,ty,tz, c,mc,twoc);
                rq[7] = setup_ray(a2.y,a2.z,a2.w, b2.y,b2.z,b2.w, r00,r10,r20, tx,ty,tz, c,mc,twoc);
            }
        } else {
            #pragma unroll
            for (int k = 0; k < 8; ++k) {
                int i = base + k;
                if (i < n) {
                    rq[k] = setup_ray(P[3*i],P[3*i+1],P[3*i+2],
                                      V[3*i],V[3*i+1],V[3*i+2],
                                      r00,r10,r20, tx,ty,tz, c,mc,twoc);
                } else {
                    rq[k].E = 2.0f; rq[k].s = 1.0f; rq[k].i4 = 0.25f; // F ends 0
                }
            }
        }

        const u64 TWO2 = 0x4000000040000000ULL;  // (2, 2)
        const u64 ONE2 = 0x3F8000003F800000ULL;  // (1, 1)

        u64 E[4], p[4], q[4], I4[4];
        #pragma unroll
        for (int k = 0; k < 4; ++k) {
            E[k]  = pk2(rq[2*k].E,  rq[2*k+1].E);
            p[k]  = pk2(rq[2*k].s,  rq[2*k+1].s);   // s = p/q, q0 = 1
            q[k]  = ONE2;
            I4[k] = pk2(rq[2*k].i4, rq[2*k+1].i4);
        }

        // Projective LM: s' = s(s^2+E)/(2s^2+1)
        //   p' = p (p^2 + E q^2),  q' = q (2 p^2 + q^2)
        // ROLLED loop: 15 x (2 iterations + exact power-of-two renorm) + 1 tail
        // iteration. Bit-identical trajectory to the fully-unrolled version,
        // but the body (~1 KB) now fits the 6 KB L0 I-cache.
        #pragma unroll 1
        for (int blk = 0; blk < NITER / 2; ++blk) {
            #pragma unroll
            for (int sub = 0; sub < 2; ++sub) {
                #pragma unroll
                for (int k = 0; k < 4; ++k) {
                    u64 pp = fmul2(p[k], p[k]);
                    u64 qq = fmul2(q[k], q[k]);
                    u64 u  = ffma2(E[k], qq, pp);    // p^2 + E q^2
                    u64 v  = ffma2(pp, TWO2, qq);    // 2 p^2 + q^2
                    p[k] = fmul2(p[k], u);
                    q[k] = fmul2(q[k], v);
                }
            }
            #pragma unroll
            for (int k = 0; k < 4; ++k) {
                u64 sc = exp_scale(q[k]);    // 2^-e per half (int ops, exact)
                p[k] = fmul2(p[k], sc);      // exact
                q[k] = set_exp1(q[k]);       // exact, alu pipe only
            }
        }
        // tail iteration (it = 30, even: no renorm follows)
        #pragma unroll
        for (int k = 0; k < 4; ++k) {
            u64 pp = fmul2(p[k], p[k]);
            u64 qq = fmul2(q[k], q[k]);
            u64 u  = ffma2(E[k], qq, pp);
            u64 v  = ffma2(pp, TWO2, qq);
            p[k] = fmul2(p[k], u);
            q[k] = fmul2(q[k], v);
        }

        // Epilogue: s = p/q, F = (s^2 - D) i4 = (s^2 - E + 1) i4
        u64 ss = 0ULL;
        #pragma unroll
        for (int k = 0; k < 4; ++k) {
            float qa, qb; up2(q[k], qa, qb);
            u64 rq2 = pk2(frcp_(qa), frcp_(qb));
            u64 s  = fmul2(p[k], rq2);
            u64 qs = fmul2(s, s);
            u64 t  = fsub2(qs, E[k]);            // s^2 - D - 1
            u64 w  = fadd2(t, ONE2);             // s^2 - D
            u64 F  = fmul2(w, I4[k]);
            ss = ffma2(F, F, ss);
        }
        float sa, sb; up2(ss, sa, sb);
        ssum = sa + sb;
    }

    // Block tree reduction (float)
    #pragma unroll
    for (int o = 16; o > 0; o >>= 1)
        ssum += __shfl_xor_sync(0xffffffffu, ssum, o);
    __shared__ float wsum[BLOCK / 32];
    if ((threadIdx.x & 31) == 0) wsum[threadIdx.x >> 5] = ssum;
    __syncthreads();

    // Global double accumulation + last-block finalize (self-resetting for
    // identical behavior on every graph replay).
    if (threadIdx.x == 0) {
        float bsum = 0.0f;
        #pragma unroll
        for (int w = 0; w < BLOCK / 32; ++w) bsum += wsum[w];
        atomicAdd(&g_sum, (double)bsum);
        __threadfence();
        unsigned old = atomicAdd(&g_count, 1u);
        if (old == gridDim.x - 1) {
            __threadfence();
            double tot = g_sum;
            out[0] = (float)((double)loss_in[0] + tot * invN);
            g_sum = 0.0;
            __threadfence();
            g_count = 0;
        }
    }
}

extern "C" void kernel_launch(void* const* d_in, const int* in_sizes, int n_in,
                              void* d_out, int out_size)
{
    const float* P       = (const float*)d_in[0];
    const float* V       = (const float*)d_in[1];
    const float* R       = (const float*)d_in[2];
    const float* T       = (const float*)d_in[3];
    const float* c       = (const float*)d_in[4];
    const float* loss_in = (const float*)d_in[5];

    const int n = in_sizes[0] / 3;                 // number of rays
    int nthreads = (n + 7) / 8;                    // 8 rays per thread
    int nblocks  = (nthreads + BLOCK - 1) / BLOCK; // 2048 for N=4.19M

    lm_kernel<<<nblocks, BLOCK>>>(P, V, R, T, c, loss_in,
                                  (float*)d_out, n, 1.0 / (double)n);
}

// round 16
// speedup vs baseline: 1.0118x; 1.0059x over previous
#include <cuda_runtime.h>

typedef unsigned long long u64;

#define NITER 31
#define BLOCK 256
#define RAYS_PB (BLOCK * 8)   // 2048 rays per block

__device__ double   g_sum   = 0.0;
__device__ unsigned g_count = 0;

__device__ __forceinline__ u64 pk2(float a, float b) {
    u64 r; asm("mov.b64 %0, {%1, %2};" : "=l"(r) : "f"(a), "f"(b)); return r;
}
__device__ __forceinline__ void up2(u64 v, float &a, float &b) {
    asm("mov.b64 {%0, %1}, %2;" : "=f"(a), "=f"(b) : "l"(v));
}
__device__ __forceinline__ u64 ffma2(u64 a, u64 b, u64 c) {
    u64 d; asm("fma.rn.f32x2 %0, %1, %2, %3;" : "=l"(d) : "l"(a), "l"(b), "l"(c)); return d;
}
__device__ __forceinline__ u64 fmul2(u64 a, u64 b) {
    u64 d; asm("mul.rn.f32x2 %0, %1, %2;" : "=l"(d) : "l"(a), "l"(b)); return d;
}
__device__ __forceinline__ u64 fsub2(u64 a, u64 b) {
    u64 d; asm("sub.rn.f32x2 %0, %1, %2;" : "=l"(d) : "l"(a), "l"(b)); return d;
}
__device__ __forceinline__ u64 fadd2(u64 a, u64 b) {
    u64 d; asm("add.rn.f32x2 %0, %1, %2;" : "=l"(d) : "l"(a), "l"(b)); return d;
}
__device__ __forceinline__ float frcp_(float x) {
    float r; asm("rcp.approx.f32 %0, %1;" : "=f"(r) : "f"(x)); return r;
}
// Exact common power-of-two renorm scale from q's exponent (u64 int ops).
__device__ __forceinline__ u64 exp_scale(u64 q) {
    return 0x7F0000007F000000ULL - (q & 0x7F8000007F800000ULL);
}
// Force positive-normal q's exponent to 127 (== fmul2(q, exp_scale(q)) exactly).
__device__ __forceinline__ u64 set_exp1(u64 q) {
    return (q & 0x807FFFFF807FFFFFULL) | 0x3F8000003F800000ULL;
}

// Per-ray quadratic: A = -c(1-vlx^2), B = vlx + 2c(plx*vlx - (P-T).V),
// C = plx + c(plx^2 - |P-T|^2), D = B^2 - 4AC.  (|V|=1, rotation invariance.)
__device__ __forceinline__ void setup_ray(
    float px, float py, float pz, float wx, float wy, float wz,
    float r00, float r10, float r20, float tx, float ty, float tz,
    float c, float mc, float twoc,
    float &B, float &D, float &i4)
{
    float qx = px - tx, qy = py - ty, qz = pz - tz;
    float plx  = qx*r00 + qy*r10 + qz*r20;
    float vlx  = wx*r00 + wy*r10 + wz*r20;
    float ndot = fmaf(-qx, wx, fmaf(-qy, wy, -qz*wz));   // -(P-T).V
    float nn2  = fmaf(-qx, qx, fmaf(-qy, qy, -qz*qz));   // -|P-T|^2
    float A = fmaf(vlx*vlx, c, mc);
    B = fmaf(twoc, fmaf(plx, vlx, ndot), vlx);
    float C = fmaf(c, fmaf(plx, plx, nn2), plx);
    if (A == 0.0f) { A = 1.0f; B = 1.0f; C = 0.0f; }     // degenerate guard
    D  = fmaf(A * C, -4.0f, B * B);
    i4 = frcp_(4.0f * A);
}

__global__ void __launch_bounds__(BLOCK)
lm_kernel(const float* __restrict__ P, const float* __restrict__ V,
          const float* __restrict__ R, const float* __restrict__ T,
          const float* __restrict__ Cs, const float* __restrict__ loss_in,
          float* __restrict__ out, int n, double invN)
{
    __shared__ float sB[RAYS_PB];
    __shared__ float sE[RAYS_PB];
    __shared__ float sI[RAYS_PB];
    __shared__ int   s_cnt;
    __shared__ float wsum[BLOCK / 32];

    if (threadIdx.x == 0) s_cnt = 0;
    __syncthreads();

    const int g    = blockIdx.x * BLOCK + threadIdx.x;
    const int base = g * 8;
    const unsigned lane = threadIdx.x & 31u;

    const float r00 = __ldg(R + 0), r10 = __ldg(R + 3), r20 = __ldg(R + 6);
    const float tx = __ldg(T + 0), ty = __ldg(T + 1), tz = __ldg(T + 2);
    const float c    = __ldg(Cs);
    const float mc   = -c;
    const float twoc = 2.0f * c;

    // ---- phase 1: setup + classify all 8 rays of this thread ----
    float rB[8], rD[8], rI[8];
    bool  valid[8];
    if (base + 8 <= n) {
        const float4* P4 = (const float4*)P;
        const float4* V4 = (const float4*)V;
        #pragma unroll
        for (int h = 0; h < 2; ++h) {
            float4 a0 = P4[6*g + 3*h + 0], a1 = P4[6*g + 3*h + 1], a2 = P4[6*g + 3*h + 2];
            float4 b0 = V4[6*g + 3*h + 0], b1 = V4[6*g + 3*h + 1], b2 = V4[6*g + 3*h + 2];
            setup_ray(a0.x,a0.y,a0.z, b0.x,b0.y,b0.z, r00,r10,r20, tx,ty,tz, c,mc,twoc,
                      rB[4*h+0], rD[4*h+0], rI[4*h+0]);
            setup_ray(a0.w,a1.x,a1.y, b0.w,b1.x,b1.y, r00,r10,r20, tx,ty,tz, c,mc,twoc,
                      rB[4*h+1], rD[4*h+1], rI[4*h+1]);
            setup_ray(a1.z,a1.w,a2.x, b1.z,b1.w,b2.x, r00,r10,r20, tx,ty,tz, c,mc,twoc,
                      rB[4*h+2], rD[4*h+2], rI[4*h+2]);
            setup_ray(a2.y,a2.z,a2.w, b2.y,b2.z,b2.w, r00,r10,r20, tx,ty,tz, c,mc,twoc,
                      rB[4*h+3], rD[4*h+3], rI[4*h+3]);
        }
        #pragma unroll
        for (int k = 0; k < 8; ++k) valid[k] = true;
    } else {
        #pragma unroll
        for (int k = 0; k < 8; ++k) {
            int i = base + k;
            valid[k] = (i < n);
            if (valid[k]) {
                setup_ray(P[3*i],P[3*i+1],P[3*i+2], V[3*i],V[3*i+1],V[3*i+2],
                          r00,r10,r20, tx,ty,tz, c,mc,twoc, rB[k], rD[k], rI[k]);
            } else { rB[k] = 1.0f; rD[k] = 1.0f; rI[k] = 0.0f; }
        }
    }

    // ---- classify + warp-aggregated compaction into smem ----
    // Skip (F ~ 0) iff the LM map provably converges to +-sqrt(D) within 31
    // iters: 0.2 < D < 3.4 (monotone regime, decent contraction 1/(2D+1))
    // and |B| large enough to escape the repelling fixed point at 0 within
    // ~18 iterations (growth rate E per iter near 0): |B| > sqrt(D) * E^-18.
    #pragma unroll
    for (int k = 0; k < 8; ++k) {
        float D = rD[k], B = rB[k];
        bool conv = (D > 0.2f) && (D < 3.4f) &&
                    (fabsf(B) > sqrtf(D) * exp2f(-18.0f * log2f(D + 1.0f)));
        bool push = valid[k] && !conv;
        unsigned m = __ballot_sync(0xffffffffu, push);
        int nw = __popc((int)m);
        if (nw) {
            int ldr = __ffs(m) - 1;
            int b0 = 0;
            if ((int)lane == ldr) b0 = atomicAdd(&s_cnt, nw);
            b0 = __shfl_sync(0xffffffffu, b0, ldr);
            if (push) {
                int pos = b0 + __popc((int)(m & ((1u << lane) - 1u)));
                sB[pos] = B;
                sE[pos] = D + 1.0f;
                sI[pos] = rI[k];
            }
        }
    }
    __syncthreads();
    const int cnt = s_cnt;

    const u64 TWO2 = 0x4000000040000000ULL;  // (2, 2)
    const u64 ONE2 = 0x3F8000003F800000ULL;  // (1, 1)

    float ssum = 0.0f;

    // ---- phase 2: iterate only the compacted rays, 4 per thread per round ----
    const int per_round = BLOCK * 4;
    const int rounds = (cnt + per_round - 1) / per_round;
    for (int r = 0; r < rounds; ++r) {
        // warp-uniform skip of fully-empty warps (no syncs inside this loop)
        int wbase = r * per_round + (int)(threadIdx.x & ~31u) * 4;
        if (wbase >= cnt) continue;

        int j0 = r * per_round + threadIdx.x * 4;
        u64 E[2], p[2], q[2], I4[2];
        #pragma unroll
        for (int k2 = 0; k2 < 2; ++k2) {
            int j = j0 + 2 * k2;
            float b0 = 1.0f, e0 = 2.0f, i0 = 0.0f;   // dummy: fixed point, F=0
            float b1 = 1.0f, e1 = 2.0f, i1 = 0.0f;
            if (j     < cnt) { b0 = sB[j];     e0 = sE[j];     i0 = sI[j];     }
            if (j + 1 < cnt) { b1 = sB[j + 1]; e1 = sE[j + 1]; i1 = sI[j + 1]; }
            E[k2]  = pk2(e0, e1);
            p[k2]  = pk2(b0, b1);
            q[k2]  = ONE2;
            I4[k2] = pk2(i0, i1);
        }

        // Projective LM (R13-validated): p' = p(p^2+Eq^2), q' = q(2p^2+q^2),
        // exact common power-of-two renorm every 2nd iteration.
        #pragma unroll
        for (int it = 0; it < NITER; ++it) {
            #pragma unroll
            for (int k2 = 0; k2 < 2; ++k2) {
                u64 pp = fmul2(p[k2], p[k2]);
                u64 qq = fmul2(q[k2], q[k2]);
                u64 u  = ffma2(E[k2], qq, pp);
                u64 v  = ffma2(pp, TWO2, qq);
                p[k2] = fmul2(p[k2], u);
                q[k2] = fmul2(q[k2], v);
            }
            if (it & 1) {
                #pragma unroll
                for (int k2 = 0; k2 < 2; ++k2) {
                    u64 sc = exp_scale(q[k2]);
                    p[k2] = fmul2(p[k2], sc);
                    q[k2] = set_exp1(q[k2]);
                }
            }
        }

        // Epilogue: s = p/q, F = (s^2 - E + 1) * i4; accumulate F^2
        #pragma unroll
        for (int k2 = 0; k2 < 2; ++k2) {
            float qa, qb; up2(q[k2], qa, qb);
            u64 rq2 = pk2(frcp_(qa), frcp_(qb));
            u64 s  = fmul2(p[k2], rq2);
            u64 qs = fmul2(s, s);
            u64 t  = fsub2(qs, E[k2]);
            u64 w  = fadd2(t, ONE2);
            u64 F  = fmul2(w, I4[k2]);
            u64 F2 = fmul2(F, F);
            float fa, fb; up2(F2, fa, fb);
            ssum += fa + fb;
        }
    }

    // ---- block tree reduction ----
    #pragma unroll
    for (int o = 16; o > 0; o >>= 1)
        ssum += __shfl_xor_sync(0xffffffffu, ssum, o);
    if ((threadIdx.x & 31) == 0) wsum[threadIdx.x >> 5] = ssum;
    __syncthreads();

    // Global double accumulation + last-block finalize (self-resetting for
    // identical behavior on every graph replay).
    if (threadIdx.x == 0) {
        float bsum = 0.0f;
        #pragma unroll
        for (int w = 0; w < BLOCK / 32; ++w) bsum += wsum[w];
        atomicAdd(&g_sum, (double)bsum);
        __threadfence();
        unsigned old = atomicAdd(&g_count, 1u);
        if (old == gridDim.x - 1) {
            __threadfence();
            double tot = g_sum;
            out[0] = (float)((double)loss_in[0] + tot * invN);
            g_sum = 0.0;
            __threadfence();
            g_count = 0;
        }
    }
}

extern "C" void kernel_launch(void* const* d_in, const int* in_sizes, int n_in,
                              void* d_out, int out_size)
{
    const float* P       = (const float*)d_in[0];
    const float* V       = (const float*)d_in[1];
    const float* R       = (const float*)d_in[2];
    const float* T       = (const float*)d_in[3];
    const float* c       = (const float*)d_in[4];
    const float* loss_in = (const float*)d_in[5];

    const int n = in_sizes[0] / 3;                 // number of rays
    int nblocks = (n + RAYS_PB - 1) / RAYS_PB;     // 2048 for N=4.19M

    lm_kernel<<<nblocks, BLOCK>>>(P, V, R, T, c, loss_in,
                                  (float*)d_out, n, 1.0 / (double)n);
}

// round 17
// speedup vs baseline: 1.1722x; 1.1585x over previous
#include <cuda_runtime.h>

typedef unsigned long long u64;

#define NITER 31
#define BLOCK 256
#define RAYS_PB (BLOCK * 8)   // 2048 rays per block

__device__ double   g_sum   = 0.0;
__device__ unsigned g_count = 0;

__device__ __forceinline__ u64 pk2(float a, float b) {
    u64 r; asm("mov.b64 %0, {%1, %2};" : "=l"(r) : "f"(a), "f"(b)); return r;
}
__device__ __forceinline__ void up2(u64 v, float &a, float &b) {
    asm("mov.b64 {%0, %1}, %2;" : "=f"(a), "=f"(b) : "l"(v));
}
__device__ __forceinline__ u64 ffma2(u64 a, u64 b, u64 c) {
    u64 d; asm("fma.rn.f32x2 %0, %1, %2, %3;" : "=l"(d) : "l"(a), "l"(b), "l"(c)); return d;
}
__device__ __forceinline__ u64 fmul2(u64 a, u64 b) {
    u64 d; asm("mul.rn.f32x2 %0, %1, %2;" : "=l"(d) : "l"(a), "l"(b)); return d;
}
__device__ __forceinline__ u64 fsub2(u64 a, u64 b) {
    u64 d; asm("sub.rn.f32x2 %0, %1, %2;" : "=l"(d) : "l"(a), "l"(b)); return d;
}
__device__ __forceinline__ u64 fadd2(u64 a, u64 b) {
    u64 d; asm("add.rn.f32x2 %0, %1, %2;" : "=l"(d) : "l"(a), "l"(b)); return d;
}
__device__ __forceinline__ float frcp_(float x) {
    float r; asm("rcp.approx.f32 %0, %1;" : "=f"(r) : "f"(x)); return r;
}
// Exact common power-of-two renorm scale from q's exponent (u64 int ops).
__device__ __forceinline__ u64 exp_scale(u64 q) {
    return 0x7F0000007F000000ULL - (q & 0x7F8000007F800000ULL);
}
// Force positive-normal q's exponent to 127 (== fmul2(q, exp_scale(q)) exactly).
__device__ __forceinline__ u64 set_exp1(u64 q) {
    return (q & 0x807FFFFF807FFFFFULL) | 0x3F8000003F800000ULL;
}

// Per-ray quadratic: A = -c(1-vlx^2), B = vlx + 2c(plx*vlx - (P-T).V),
// C = plx + c(plx^2 - |P-T|^2), D = B^2 - 4AC.  (|V|=1, rotation invariance.)
__device__ __forceinline__ void setup_ray(
    float px, float py, float pz, float wx, float wy, float wz,
    float r00, float r10, float r20, float tx, float ty, float tz,
    float c, float mc, float twoc,
    float &B, float &D, float &i4)
{
    float qx = px - tx, qy = py - ty, qz = pz - tz;
    float plx  = qx*r00 + qy*r10 + qz*r20;
    float vlx  = wx*r00 + wy*r10 + wz*r20;
    float ndot = fmaf(-qx, wx, fmaf(-qy, wy, -qz*wz));   // -(P-T).V
    float nn2  = fmaf(-qx, qx, fmaf(-qy, qy, -qz*qz));   // -|P-T|^2
    float A = fmaf(vlx*vlx, c, mc);
    B = fmaf(twoc, fmaf(plx, vlx, ndot), vlx);
    float C = fmaf(c, fmaf(plx, plx, nn2), plx);
    if (A == 0.0f) { A = 1.0f; B = 1.0f; C = 0.0f; }     // degenerate guard
    D  = fmaf(A * C, -4.0f, B * B);
    i4 = frcp_(4.0f * A);
}

__global__ void __launch_bounds__(BLOCK)
lm_kernel(const float* __restrict__ P, const float* __restrict__ V,
          const float* __restrict__ R, const float* __restrict__ T,
          const float* __restrict__ Cs, const float* __restrict__ loss_in,
          float* __restrict__ out, int n, double invN)
{
    __shared__ float sB[RAYS_PB];
    __shared__ float sE[RAYS_PB];
    __shared__ float sI[RAYS_PB];
    __shared__ int   s_cnt;
    __shared__ float wsum[BLOCK / 32];

    if (threadIdx.x == 0) s_cnt = 0;
    __syncthreads();

    const int g    = blockIdx.x * BLOCK + threadIdx.x;
    const int base = g * 8;
    const unsigned lane = threadIdx.x & 31u;

    const float r00 = __ldg(R + 0), r10 = __ldg(R + 3), r20 = __ldg(R + 6);
    const float tx = __ldg(T + 0), ty = __ldg(T + 1), tz = __ldg(T + 2);
    const float c    = __ldg(Cs);
    const float mc   = -c;
    const float twoc = 2.0f * c;

    float ssum = 0.0f;

    // ---- phase 1: setup all 8 rays of this thread ----
    float rB[8], rD[8], rI[8];
    bool  valid[8];
    if (base + 8 <= n) {
        const float4* P4 = (const float4*)P;
        const float4* V4 = (const float4*)V;
        #pragma unroll
        for (int h = 0; h < 2; ++h) {
            float4 a0 = P4[6*g + 3*h + 0], a1 = P4[6*g + 3*h + 1], a2 = P4[6*g + 3*h + 2];
            float4 b0 = V4[6*g + 3*h + 0], b1 = V4[6*g + 3*h + 1], b2 = V4[6*g + 3*h + 2];
            setup_ray(a0.x,a0.y,a0.z, b0.x,b0.y,b0.z, r00,r10,r20, tx,ty,tz, c,mc,twoc,
                      rB[4*h+0], rD[4*h+0], rI[4*h+0]);
            setup_ray(a0.w,a1.x,a1.y, b0.w,b1.x,b1.y, r00,r10,r20, tx,ty,tz, c,mc,twoc,
                      rB[4*h+1], rD[4*h+1], rI[4*h+1]);
            setup_ray(a1.z,a1.w,a2.x, b1.z,b1.w,b2.x, r00,r10,r20, tx,ty,tz, c,mc,twoc,
                      rB[4*h+2], rD[4*h+2], rI[4*h+2]);
            setup_ray(a2.y,a2.z,a2.w, b2.y,b2.z,b2.w, r00,r10,r20, tx,ty,tz, c,mc,twoc,
                      rB[4*h+3], rD[4*h+3], rI[4*h+3]);
        }
        #pragma unroll
        for (int k = 0; k < 8; ++k) valid[k] = true;
    } else {
        #pragma unroll
        for (int k = 0; k < 8; ++k) {
            int i = base + k;
            valid[k] = (i < n);
            if (valid[k]) {
                setup_ray(P[3*i],P[3*i+1],P[3*i+2], V[3*i],V[3*i+1],V[3*i+2],
                          r00,r10,r20, tx,ty,tz, c,mc,twoc, rB[k], rD[k], rI[k]);
            } else { rB[k] = 1.0f; rD[k] = 1.0f; rI[k] = 0.0f; }
        }
    }

    // ---- classify + closed forms + warp-aggregated compaction ----
    // (a) D > 0.2 and B^2 > 0.0014 D  (escape+converge to +-sqrt(D) provable
    //     in 31 iters; attracting fixed point, rate 1/(2D+1)): F ~ 0, skip.
    // (b) -1.95 < D < -0.05 with B^2 r^62 < |D|*7.6e-6, r = max(|1+D|, 1/2)
    //     (|s'/s| <= r globally; s -> 0): F = -D/(4A) CLOSED FORM, accumulate.
    // (c) everything else (slow band near 0, chaotic D<=-2, tiny-B): iterate.
    #pragma unroll
    for (int k = 0; k < 8; ++k) {
        float D = rD[k], B = rB[k], i4 = rI[k];
        float B2 = B * B;
        bool conv_pos = (D > 0.2f) && (B2 > 0.0014f * D);
        float rr = fmaxf(fabsf(1.0f + D), 0.5f);
        bool conv_neg = (D < -0.05f) && (D > -1.95f) &&
                        (B2 * exp2f(62.0f * log2f(rr)) < -D * 7.6e-6f);
        if (valid[k] && conv_neg) {
            float F = D * i4;            // (-D)*i4 squared == (D*i4)^2
            ssum += F * F;
        }
        bool push = valid[k] && !conv_pos && !conv_neg;
        unsigned m = __ballot_sync(0xffffffffu, push);
        int nw = __popc((int)m);
        if (nw) {
            int ldr = __ffs(m) - 1;
            int b0 = 0;
            if ((int)lane == ldr) b0 = atomicAdd(&s_cnt, nw);
            b0 = __shfl_sync(0xffffffffu, b0, ldr);
            if (push) {
                int pos = b0 + __popc((int)(m & ((1u << lane) - 1u)));
                sB[pos] = B;
                sE[pos] = D + 1.0f;
                sI[pos] = i4;
            }
        }
    }
    __syncthreads();
    const int cnt = s_cnt;

    const u64 TWO2 = 0x4000000040000000ULL;  // (2, 2)
    const u64 ONE2 = 0x3F8000003F800000ULL;  // (1, 1)

    // ---- phase 2: iterate only the compacted rays, 4 per thread per round ----
    const int per_round = BLOCK * 4;
    const int rounds = (cnt + per_round - 1) / per_round;
    for (int r = 0; r < rounds; ++r) {
        int wbase = r * per_round + (int)(threadIdx.x & ~31u) * 4;
        if (wbase >= cnt) continue;          // warp-uniform skip

        int j0 = r * per_round + threadIdx.x * 4;
        u64 E[2], p[2], q[2], I4[2];
        #pragma unroll
        for (int k2 = 0; k2 < 2; ++k2) {
            int j = j0 + 2 * k2;
            float b0 = 1.0f, e0 = 2.0f, i0 = 0.0f;   // dummy: fixed point, F=0
            float b1 = 1.0f, e1 = 2.0f, i1 = 0.0f;
            if (j     < cnt) { b0 = sB[j];     e0 = sE[j];     i0 = sI[j];     }
            if (j + 1 < cnt) { b1 = sB[j + 1]; e1 = sE[j + 1]; i1 = sI[j + 1]; }
            E[k2]  = pk2(e0, e1);
            p[k2]  = pk2(b0, b1);
            q[k2]  = ONE2;
            I4[k2] = pk2(i0, i1);
        }

        // Projective LM (R13-validated): p' = p(p^2+Eq^2), q' = q(2p^2+q^2),
        // exact common power-of-two renorm every 2nd iteration.
        #pragma unroll
        for (int it = 0; it < NITER; ++it) {
            #pragma unroll
            for (int k2 = 0; k2 < 2; ++k2) {
                u64 pp = fmul2(p[k2], p[k2]);
                u64 qq = fmul2(q[k2], q[k2]);
                u64 u  = ffma2(E[k2], qq, pp);
                u64 v  = ffma2(pp, TWO2, qq);
                p[k2] = fmul2(p[k2], u);
                q[k2] = fmul2(q[k2], v);
            }
            if (it & 1) {
                #pragma unroll
                for (int k2 = 0; k2 < 2; ++k2) {
                    u64 sc = exp_scale(q[k2]);
                    p[k2] = fmul2(p[k2], sc);
                    q[k2] = set_exp1(q[k2]);
                }
            }
        }

        // Epilogue: s = p/q, F = (s^2 - E + 1) * i4; accumulate F^2
        #pragma unroll
        for (int k2 = 0; k2 < 2; ++k2) {
            float qa, qb; up2(q[k2], qa, qb);
            u64 rq2 = pk2(frcp_(qa), frcp_(qb));
            u64 s  = fmul2(p[k2], rq2);
            u64 qs = fmul2(s, s);
            u64 t  = fsub2(qs, E[k2]);
            u64 w  = fadd2(t, ONE2);
            u64 F  = fmul2(w, I4[k2]);
            u64 F2 = fmul2(F, F);
            float fa, fb; up2(F2, fa, fb);
            ssum += fa + fb;
        }
    }

    // ---- block tree reduction ----
    #pragma unroll
    for (int o = 16; o > 0; o >>= 1)
        ssum += __shfl_xor_sync(0xffffffffu, ssum, o);
    if ((threadIdx.x & 31) == 0) wsum[threadIdx.x >> 5] = ssum;
    __syncthreads();

    // Global double accumulation + last-block finalize (self-resetting for
    // identical behavior on every graph replay).
    if (threadIdx.x == 0) {
        float bsum = 0.0f;
        #pragma unroll
        for (int w = 0; w < BLOCK / 32; ++w) bsum += wsum[w];
        atomicAdd(&g_sum, (double)bsum);
        __threadfence();
        unsigned old = atomicAdd(&g_count, 1u);
        if (old == gridDim.x - 1) {
            __threadfence();
            double tot = g_sum;
            out[0] = (float)((double)loss_in[0] + tot * invN);
            g_sum = 0.0;
            __threadfence();
            g_count = 0;
        }
    }
}

extern "C" void kernel_launch(void* const* d_in, const int* in_sizes, int n_in,
                              void* d_out, int out_size)
{
    const float* P       = (const float*)d_in[0];
    const float* V       = (const float*)d_in[1];
    const float* R       = (const float*)d_in[2];
    const float* T       = (const float*)d_in[3];
    const float* c       = (const float*)d_in[4];
    const float* loss_in = (const float*)d_in[5];

    const int n = in_sizes[0] / 3;                 // number of rays
    int nblocks = (n + RAYS_PB - 1) / RAYS_PB;     // 2048 for N=4.19M

    lm_kernel<<<nblocks, BLOCK>>>(P, V, R, T, c, loss_in,
                                  (float*)d_out, n, 1.0 / (double)n);
}